// round 3
// baseline (speedup 1.0000x reference)
#include <cuda_runtime.h>
#include <cuda_bf16.h>
#include <math.h>

// ---------------------------------------------------------------------------
// 512 independent diffusion chains; one persistent CTA (128 thr) per chain.
// ---------------------------------------------------------------------------

#define NSTEPS 50

// ---- device-global scratch (no allocations allowed) ----
__device__ float g_loc[32 * 128];
__device__ float g_scale[32 * 128];
__device__ float g_cond[6 * NSTEPS * 32];      // [l][t][c]
__device__ float g_coef[NSTEPS * 5];           // s1m, 1/sab, c0, cxt, sig
__device__ float w_inT[128 * 32];              // [d][c]
__device__ float wdilT[6 * 32 * 3 * 64];       // [l][c][k][o]
__device__ float woutT[6 * 32 * 64];           // [l][c][o]
__device__ float w_o1Ts[32 * 32];              // [c][o], pre-scaled 1/sqrt(6)
__device__ float w_o2T[32 * 128];              // [c][d]

__device__ __forceinline__ float sigm_f(float x) { return 1.0f / (1.0f + __expf(-x)); }
__device__ __forceinline__ float tanh_f(float x) { return 1.0f - 2.0f / (__expf(2.0f * x) + 1.0f); }

// ---------------------------------------------------------------------------
// Setup: weight transposes + DDPM schedule (double)
// ---------------------------------------------------------------------------
__global__ void k_prep(const float* __restrict__ w_in, const float* __restrict__ lwd,
                       const float* __restrict__ lwo, const float* __restrict__ w_o1,
                       const float* __restrict__ w_o2) {
    int i = blockIdx.x * blockDim.x + threadIdx.x;
    int nt = gridDim.x * blockDim.x;
    for (int idx = i; idx < 4096; idx += nt) {
        int d = idx >> 5, c = idx & 31;
        w_inT[idx] = w_in[c * 128 + d];
    }
    for (int idx = i; idx < 6 * 32 * 3 * 64; idx += nt) {
        int o = idx & 63, r = idx >> 6;
        int k = r % 3, r2 = r / 3;
        int c = r2 & 31, l = r2 >> 5;
        wdilT[idx] = lwd[((l * 64 + o) * 32 + c) * 3 + k];
    }
    for (int idx = i; idx < 6 * 32 * 64; idx += nt) {
        int o = idx & 63, r = idx >> 6;
        int c = r & 31, l = r >> 5;
        woutT[idx] = lwo[(l * 64 + o) * 32 + c];
    }
    for (int idx = i; idx < 1024; idx += nt) {
        int o = idx & 31, c = idx >> 5;
        w_o1Ts[idx] = w_o1[o * 32 + c] * 0.40824829046386302f;  // 1/sqrt(6)
    }
    for (int idx = i; idx < 4096; idx += nt) {
        int d = idx & 127, c = idx >> 7;
        w_o2T[idx] = w_o2[d * 32 + c];
    }
    if (i == 0) {
        double abar = 1.0;
        for (int t = 0; t < NSTEPS; t++) {
            double beta = 1e-4 + (double)t * (0.1 - 1e-4) / 49.0;
            double alpha = 1.0 - beta;
            double abar_prev = abar;
            abar *= alpha;
            double om = 1.0 - abar;
            g_coef[t * 5 + 0] = (float)sqrt(om);
            g_coef[t * 5 + 1] = (float)(1.0 / sqrt(abar));
            g_coef[t * 5 + 2] = (float)(beta * sqrt(abar_prev) / om);
            g_coef[t * 5 + 3] = (float)((1.0 - abar_prev) * sqrt(alpha) / om);
            double pv = beta * (1.0 - abar_prev) / om;
            g_coef[t * 5 + 4] = (t > 0) ? (float)sqrt(pv) : 0.0f;
        }
    }
}

// ---------------------------------------------------------------------------
// Setup: EWMA Student-t marginal fit. grid 32 (b) x 128 (d)
// ---------------------------------------------------------------------------
__global__ void k_stats(const float* __restrict__ x_hist) {
    int b = blockIdx.x, d = threadIdx.x;
    const float* xb = x_hist + (size_t)b * 192 * 128 + d;
    double s = 0.0;
    for (int t = 0; t < 192; t++) s += (double)xb[t * 128];
    float mean = (float)(s / 192.0);
    float c = xb[0] - mean;
    float v = c * c;
    for (int t = 1; t < 192; t++) {
        float cc = xb[t * 128] - mean;
        v = 0.94f * v + 0.06f * (cc * cc);
    }
    g_loc[b * 128 + d] = mean;
    g_scale[b * 128 + d] = fmaxf(sqrtf(v * 0.5f), 1e-5f);
}

// ---------------------------------------------------------------------------
// Setup: step embedding + per-layer cond. grid 50 (t) x 512 threads.
// sin/cos of the exact f32 argument, evaluated in double.
// ---------------------------------------------------------------------------
__global__ void k_temb(const float* __restrict__ w1, const float* __restrict__ b1,
                       const float* __restrict__ w2, const float* __restrict__ b2,
                       const float* __restrict__ wt, const float* __restrict__ bt) {
    __shared__ float pe[128], te1[512], te2[512];
    int t = blockIdx.x, tid = threadIdx.x;
    if (tid < 64) {
        float y = ((float)tid * 4.0f) / 63.0f;
        float p = (float)pow(10.0, (double)y);
        float e = (float)t * p;
        pe[tid] = (float)sin((double)e);
        pe[tid + 64] = (float)cos((double)e);
    }
    __syncthreads();
    {
        double a = (double)b1[tid];
        for (int j = 0; j < 128; j++) a += (double)pe[j] * (double)w1[j * 512 + tid];
        te1[tid] = (float)(a / (1.0 + exp(-a)));
    }
    __syncthreads();
    {
        double a = (double)b2[tid];
        for (int k = 0; k < 512; k++) a += (double)te1[k] * (double)w2[k * 512 + tid];
        te2[tid] = (float)(a / (1.0 + exp(-a)));
    }
    __syncthreads();
    if (tid < 192) {
        int l = tid >> 5, c = tid & 31;
        double a = (double)bt[l * 32 + c];
        for (int k = 0; k < 512; k++) a += (double)te2[k] * (double)wt[(l * 512 + k) * 32 + c];
        g_cond[(l * NSTEPS + t) * 32 + c] = (float)a;
    }
}

// ---------------------------------------------------------------------------
// Dilated conv core, compile-time dilation. 64 o x (2 x 12 j) over 128 thr.
// ---------------------------------------------------------------------------
template <int DIL>
__device__ __forceinline__ void conv_core(const float* __restrict__ wp, const float* hcpS,
                                          float* ybS, int oo, int j0b, float bv) {
    float acc[12];
#pragma unroll
    for (int q = 0; q < 12; q++) acc[q] = bv;
    const float* hbase = hcpS + 32 + j0b;
    for (int c = 0; c < 32; c++) {
        float w0 = wp[(c * 3 + 0) * 64];
        float w1 = wp[(c * 3 + 1) * 64];
        float w2 = wp[(c * 3 + 2) * 64];
        const float* hr = hbase + c * 88;
#pragma unroll
        for (int p = 0; p < 6; p++) {
            float2 a = *(const float2*)(hr + 2 * p);
            acc[2 * p] = fmaf(w1, a.x, acc[2 * p]);
            acc[2 * p + 1] = fmaf(w1, a.y, acc[2 * p + 1]);
        }
        if (DIL >= 2) {
#pragma unroll
            for (int p = 0; p < 6; p++) {
                float2 a = *(const float2*)(hr - DIL + 2 * p);
                acc[2 * p] = fmaf(w0, a.x, acc[2 * p]);
                acc[2 * p + 1] = fmaf(w0, a.y, acc[2 * p + 1]);
                float2 b2v = *(const float2*)(hr + DIL + 2 * p);
                acc[2 * p] = fmaf(w2, b2v.x, acc[2 * p]);
                acc[2 * p + 1] = fmaf(w2, b2v.y, acc[2 * p + 1]);
            }
        } else {
#pragma unroll
            for (int q = 0; q < 12; q++) {
                acc[q] = fmaf(w0, hr[q - 1], acc[q]);
                acc[q] = fmaf(w2, hr[q + 1], acc[q]);
            }
        }
    }
#pragma unroll
    for (int q = 0; q < 12; q++) ybS[oo * 26 + j0b + q] = acc[q];
}

// ---------------------------------------------------------------------------
// Main persistent kernel: grid 512 (chain) x 128 threads.
// ---------------------------------------------------------------------------
__global__ __launch_bounds__(128, 4) void k_main(
    const float* __restrict__ z_init, const float* __restrict__ noise,
    const float* __restrict__ b_in, const float* __restrict__ bdil,
    const float* __restrict__ bout, const float* __restrict__ b_o1,
    const float* __restrict__ b_o2, float* __restrict__ out) {
    __shared__ __align__(16) float xs[128 * 26];   // x state [d][j]
    __shared__ __align__(16) float hcp[32 * 88];   // padded h+cond [c][32+j]
    __shared__ __align__(16) float hs[32 * 26];    // h
    __shared__ __align__(16) float sk[32 * 26];    // skip
    __shared__ __align__(16) float yb[64 * 26];    // conv out / act / s

    int tid = threadIdx.x;
    int chain = blockIdx.x;

    // load z_init -> xs
    {
        const float4* zp = (const float4*)(z_init + (size_t)chain * 3072);
#pragma unroll
        for (int q = 0; q < 6; q++) {
            float4 v = zp[tid * 6 + q];
            int j = q * 4;
            xs[tid * 26 + j] = v.x; xs[tid * 26 + j + 1] = v.y;
            xs[tid * 26 + j + 2] = v.z; xs[tid * 26 + j + 3] = v.w;
        }
    }
    for (int i = tid; i < 32 * 88; i += 128) hcp[i] = 0.f;
    __syncthreads();

    const int ca = tid & 31, j0a = (tid >> 5) * 6;   // 32 x (4 x 6)
    const int oo = tid >> 1, j0b = (tid & 1) * 12;   // 64 x (2 x 12)
    const float b_in_c = b_in[ca];
    const float b_o2_d = b_o2[tid];
    const float b_o1_c = b_o1[ca];

    for (int t = NSTEPS - 1; t >= 0; t--) {
        float s1m = g_coef[t * 5 + 0], isab = g_coef[t * 5 + 1];
        float c0 = g_coef[t * 5 + 2], cxt = g_coef[t * 5 + 3], sg = g_coef[t * 5 + 4];

        // ---- A: h = relu(W_in @ x + b); zero skip ----
        {
            float acc[6];
#pragma unroll
            for (int q = 0; q < 6; q++) acc[q] = b_in_c;
            for (int d = 0; d < 128; d++) {
                float w = w_inT[d * 32 + ca];
                const float2* xp = (const float2*)&xs[d * 26 + j0a];
#pragma unroll
                for (int p = 0; p < 3; p++) {
                    float2 a = xp[p];
                    acc[2 * p] = fmaf(w, a.x, acc[2 * p]);
                    acc[2 * p + 1] = fmaf(w, a.y, acc[2 * p + 1]);
                }
            }
#pragma unroll
            for (int q = 0; q < 6; q++) {
                hs[ca * 26 + j0a + q] = fmaxf(acc[q], 0.f);
                sk[ca * 26 + j0a + q] = 0.f;
            }
        }

        // ---- residual layers ----
        for (int l = 0; l < 6; l++) {
            // B: hcp = h + cond
            float cd = g_cond[(l * NSTEPS + t) * 32 + ca];
#pragma unroll
            for (int q = 0; q < 6; q++)
                hcp[ca * 88 + 32 + j0a + q] = hs[ca * 26 + j0a + q] + cd;
            __syncthreads();

            // C: dilated conv -> yb
            {
                const float* wp = wdilT + l * (32 * 3 * 64) + oo;
                float bv = bdil[l * 64 + oo];
                switch (l) {
                    case 0: conv_core<1>(wp, hcp, yb, oo, j0b, bv); break;
                    case 1: conv_core<2>(wp, hcp, yb, oo, j0b, bv); break;
                    case 2: conv_core<4>(wp, hcp, yb, oo, j0b, bv); break;
                    case 3: conv_core<8>(wp, hcp, yb, oo, j0b, bv); break;
                    case 4: conv_core<16>(wp, hcp, yb, oo, j0b, bv); break;
                    default: conv_core<32>(wp, hcp, yb, oo, j0b, bv); break;
                }
            }
            __syncthreads();

            // D: act = tanh(filt)*sigmoid(gate), written over gate rows of yb
#pragma unroll
            for (int q = 0; q < 6; q++) {
                float g = yb[ca * 26 + j0a + q];
                float f = yb[(32 + ca) * 26 + j0a + q];
                yb[ca * 26 + j0a + q] = tanh_f(f) * sigm_f(g);
            }
            __syncthreads();

            // E: y2 = Wout @ act + b; h=(h+res)/sqrt2; skip += sk
            {
                float acc[12];
                float bo = bout[l * 64 + oo];
#pragma unroll
                for (int q = 0; q < 12; q++) acc[q] = bo;
                const float* wp = woutT + l * (32 * 64) + oo;
                for (int c = 0; c < 32; c++) {
                    float w = wp[c * 64];
                    const float2* ap = (const float2*)&yb[c * 26 + j0b];
#pragma unroll
                    for (int p = 0; p < 6; p++) {
                        float2 a = ap[p];
                        acc[2 * p] = fmaf(w, a.x, acc[2 * p]);
                        acc[2 * p + 1] = fmaf(w, a.y, acc[2 * p + 1]);
                    }
                }
                if (oo < 32) {
#pragma unroll
                    for (int q = 0; q < 12; q++) {
                        int ix = oo * 26 + j0b + q;
                        hs[ix] = (hs[ix] + acc[q]) * 0.70710678118654752f;
                    }
                } else {
#pragma unroll
                    for (int q = 0; q < 12; q++)
                        sk[(oo - 32) * 26 + j0b + q] += acc[q];
                }
            }
            __syncthreads();
        }

        // ---- F: s = relu(W_o1 @ (skip/sqrt6) + b) -> yb rows 0..31 ----
        {
            float acc[6];
#pragma unroll
            for (int q = 0; q < 6; q++) acc[q] = b_o1_c;
            for (int c = 0; c < 32; c++) {
                float w = w_o1Ts[c * 32 + ca];
                const float2* sp = (const float2*)&sk[c * 26 + j0a];
#pragma unroll
                for (int p = 0; p < 3; p++) {
                    float2 a = sp[p];
                    acc[2 * p] = fmaf(w, a.x, acc[2 * p]);
                    acc[2 * p + 1] = fmaf(w, a.y, acc[2 * p + 1]);
                }
            }
#pragma unroll
            for (int q = 0; q < 6; q++)
                yb[ca * 26 + j0a + q] = fmaxf(acc[q], 0.f);
        }
        __syncthreads();

        // ---- G: eps = W_o2 @ s + b; DDPM update of xs ----
        {
            float4 nzv[6];
            const float4* np = (const float4*)(noise +
                ((size_t)(NSTEPS - 1 - t) * 512 + chain) * 3072 + (size_t)tid * 24);
#pragma unroll
            for (int q = 0; q < 6; q++) nzv[q] = np[q];

            float acc[24];
#pragma unroll
            for (int q = 0; q < 24; q++) acc[q] = 0.f;
            for (int c = 0; c < 32; c++) {
                float w = w_o2T[c * 128 + tid];
                const float2* ap = (const float2*)&yb[c * 26];
#pragma unroll
                for (int p = 0; p < 12; p++) {
                    float2 a = ap[p];
                    acc[2 * p] = fmaf(w, a.x, acc[2 * p]);
                    acc[2 * p + 1] = fmaf(w, a.y, acc[2 * p + 1]);
                }
            }
            float nzf[24];
#pragma unroll
            for (int q = 0; q < 6; q++) {
                nzf[4 * q] = nzv[q].x; nzf[4 * q + 1] = nzv[q].y;
                nzf[4 * q + 2] = nzv[q].z; nzf[4 * q + 3] = nzv[q].w;
            }
#pragma unroll
            for (int j = 0; j < 24; j++) {
                float eps = acc[j] + b_o2_d;
                float x = xs[tid * 26 + j];
                float x0 = (x - s1m * eps) * isab;
                x0 = fminf(fmaxf(x0, -1.f), 1.f);
                xs[tid * 26 + j] = fmaf(c0, x0, fmaf(cxt, x, sg * nzf[j]));
            }
        }
        __syncthreads();
    }

    // ---- final: Gaussian -> Student-t4 marginal transform ----
    {
        int b = chain & 31;
        float lc = g_loc[b * 128 + tid];
        float scl = g_scale[b * 128 + tid];
        for (int h = 0; h < 24; h++) {
            double z = (double)xs[tid * 26 + h];
            double u = 0.5 * erfc(-z * 0.70710678118654752440);
            u = fmin(fmax(u, 1e-6), 1.0 - 1e-6);
            double a = 4.0 * u * (1.0 - u);
            a = fmin(fmax(a, 1e-12), 1.0);
            double r = sqrt(a);
            double q = 2.0 * sqrt(fmax(cos(acos(r) / 3.0) / r - 1.0, 0.0));
            double sgn = (u >= 0.5) ? 1.0 : -1.0;
            out[((size_t)chain * 24 + h) * 128 + tid] = (float)((double)lc + (double)scl * sgn * q);
        }
    }
}

extern "C" void kernel_launch(void* const* d_in, const int* in_sizes, int n_in,
                              void* d_out, int out_size) {
    const float* x_hist = (const float*)d_in[0];
    const float* z_init = (const float*)d_in[1];
    const float* noise = (const float*)d_in[2];
    const float* w_in = (const float*)d_in[3];
    const float* b_in = (const float*)d_in[4];
    const float* tw1 = (const float*)d_in[5];
    const float* tb1 = (const float*)d_in[6];
    const float* tw2 = (const float*)d_in[7];
    const float* tb2 = (const float*)d_in[8];
    const float* lwt = (const float*)d_in[9];
    const float* lbt = (const float*)d_in[10];
    const float* lwd = (const float*)d_in[11];
    const float* lbd = (const float*)d_in[12];
    const float* lwo = (const float*)d_in[13];
    const float* lbo = (const float*)d_in[14];
    const float* w_o1 = (const float*)d_in[15];
    const float* b_o1 = (const float*)d_in[16];
    const float* w_o2 = (const float*)d_in[17];
    const float* b_o2 = (const float*)d_in[18];
    float* out = (float*)d_out;

    k_prep<<<64, 256>>>(w_in, lwd, lwo, w_o1, w_o2);
    k_stats<<<32, 128>>>(x_hist);
    k_temb<<<50, 512>>>(tw1, tb1, tw2, tb2, lwt, lbt);
    k_main<<<512, 128>>>(z_init, noise, b_in, lbd, lbo, b_o1, b_o2, out);
}